// round 4
// baseline (speedup 1.0000x reference)
#include <cuda_runtime.h>

// PeakSense: out[b,p] = sum_i exp(-0.5*(mass[b,i]-mu[p])^2 * exp(-lv[p])) * iv[b,i],
// terms with arg < -10 dropped. Masses sorted per batch -> per-peak window.
//
// R4: batch-interleaved searches. mu/lv (hence search targets) are batch-
// independent, so each thread runs binary searches for TWO batches in
// lockstep: 2 independent dependent-chains -> 2 searches in ~1 search latency.
// Window loops for the two batches use independent accumulators.

#define PS_B 128
#define PS_L 4096
#define PS_N 256
#define GROUPS 8                          // blocks per batch-pair in x
#define PEAKS_PER_BLOCK (PS_N / GROUPS)   // 32
#define LANES 8                           // lanes per peak
#define THREADS (PEAKS_PER_BLOCK * LANES) // 256
#define BATCHES 2                         // batches per CTA
#define LOG2E 1.4426950408889634f

__global__ __launch_bounds__(THREADS)
void peaksense_kernel(const float* __restrict__ mu,
                      const float* __restrict__ lv,
                      const float* __restrict__ masses,
                      const float* __restrict__ intens,
                      float* __restrict__ out) {
    const int tid  = threadIdx.x;
    const int p    = blockIdx.x * PEAKS_PER_BLOCK + (tid >> 3);
    const int q    = tid & 7;             // lane within peak group
    const int lane = tid & 31;
    const int b0   = blockIdx.y * BATCHES;
    const int b1   = b0 + 1;

    const float* __restrict__ mass0 = masses + (size_t)b0 * PS_L;
    const float* __restrict__ iv0   = intens + (size_t)b0 * PS_L;
    const float* __restrict__ mass1 = masses + (size_t)b1 * PS_L;
    const float* __restrict__ iv1   = intens + (size_t)b1 * PS_L;

    const float m      = mu[p];
    const float inv_s2 = __expf(-lv[p]);  // 1/sigma^2
    // arg >= -10  <=>  d^2 <= 20/inv_s2. Inflate R slightly so [lo,hi) is a
    // superset of the passing set; the exact in-loop select is the filter.
    const float R   = sqrtf(20.0f / inv_s2) * 1.0002f + 1e-5f;
    const float lob = m - R;
    const float hib = m + R;

    // Lanes 0-3 of each peak group search lo (first >= lob), lanes 4-7 search
    // hi (first > hib). Each thread runs the search for BOTH batches in
    // lockstep: the two loads per round are independent (MLP=2 on the chain).
    const bool  isLo   = (q < 4);
    const float target = isLo ? lob : hib;

    int lo0 = 0, hi0 = PS_L, lo1 = 0, hi1 = PS_L;
    #pragma unroll 1
    for (int it = 0; it < 12; ++it) {     // ceil(log2(4096)) = 12 rounds max
        int  mid0 = (lo0 + hi0) >> 1;
        int  mid1 = (lo1 + hi1) >> 1;
        bool a0 = lo0 < hi0;
        bool a1 = lo1 < hi1;
        float v0 = a0 ? mass0[mid0] : 0.0f;
        float v1 = a1 ? mass1[mid1] : 0.0f;
        if (a0) {
            bool g = isLo ? (v0 < target) : (v0 <= target);
            if (g) lo0 = mid0 + 1; else hi0 = mid0;
        }
        if (a1) {
            bool g = isLo ? (v1 < target) : (v1 <= target);
            if (g) lo1 = mid1 + 1; else hi1 = mid1;
        }
    }

    // Broadcast bounds within the 8-lane peak group.
    const int base = lane & ~7;
    const int wlo0 = __shfl_sync(0xFFFFFFFF, lo0, base + 0);
    const int whi0 = __shfl_sync(0xFFFFFFFF, lo0, base + 4);
    const int wlo1 = __shfl_sync(0xFFFFFFFF, lo1, base + 0);
    const int whi1 = __shfl_sync(0xFFFFFFFF, lo1, base + 4);

    // w = exp2(c2*d*d), keep iff c2*d*d >= -10*log2(e).
    const float c2  = -0.5f * inv_s2 * LOG2E;
    const float th2 = -10.0f * LOG2E;

    // Two independent window loops (independent accumulators; short trips).
    float acc0 = 0.0f, acc1 = 0.0f;
    {
        int i0 = wlo0 + q;
        int i1 = wlo1 + q;
        // Jointly strided loop while both active maximizes load-level ILP.
        #pragma unroll 1
        while (i0 < whi0 && i1 < whi1) {
            float x0 = mass0[i0], y0 = iv0[i0];
            float x1 = mass1[i1], y1 = iv1[i1];
            float d0 = x0 - m, d1 = x1 - m;
            float a0 = c2 * d0 * d0, a1 = c2 * d1 * d1;
            float w0 = (a0 >= th2) ? exp2f(a0) : 0.0f;
            float w1 = (a1 >= th2) ? exp2f(a1) : 0.0f;
            acc0 = fmaf(w0, y0, acc0);
            acc1 = fmaf(w1, y1, acc1);
            i0 += LANES; i1 += LANES;
        }
        #pragma unroll 2
        for (; i0 < whi0; i0 += LANES) {
            float d = mass0[i0] - m;
            float a = c2 * d * d;
            float w = (a >= th2) ? exp2f(a) : 0.0f;
            acc0 = fmaf(w, iv0[i0], acc0);
        }
        #pragma unroll 2
        for (; i1 < whi1; i1 += LANES) {
            float d = mass1[i1] - m;
            float a = c2 * d * d;
            float w = (a >= th2) ? exp2f(a) : 0.0f;
            acc1 = fmaf(w, iv1[i1], acc1);
        }
    }

    // Reduce the 8 lanes of this peak for both batches.
    #pragma unroll
    for (int s = 1; s < 8; s <<= 1) {
        acc0 += __shfl_xor_sync(0xFFFFFFFF, acc0, s);
        acc1 += __shfl_xor_sync(0xFFFFFFFF, acc1, s);
    }

    if (q == 0) {
        out[(size_t)b0 * PS_N + p] = acc0;
        out[(size_t)b1 * PS_N + p] = acc1;
    }
}

extern "C" void kernel_launch(void* const* d_in, const int* in_sizes, int n_in,
                              void* d_out, int out_size) {
    const float* mu     = (const float*)d_in[0];
    const float* lv     = (const float*)d_in[1];
    const float* masses = (const float*)d_in[2];
    const float* intens = (const float*)d_in[3];
    float* out = (float*)d_out;

    dim3 grid(GROUPS, PS_B / BATCHES);
    peaksense_kernel<<<grid, THREADS>>>(mu, lv, masses, intens, out);
}

// round 5
// speedup vs baseline: 1.1910x; 1.1910x over previous
#include <cuda_runtime.h>

// PeakSense: out[b,p] = sum_i exp(-0.5*(mass[b,i]-mu[p])^2 * exp(-lv[p])) * iv[b,i],
// terms with arg < -10 dropped. Masses sorted per batch -> per-peak window.
//
// R5: R3's shape (1024 CTAs, 8 lanes/peak, lane-split lo/hi search) but with
// the mass array staged in shared memory. R4 showed the search's 12 dependent
// loads were L2 hits (~250 cyc each, ~3000 cyc chain); in smem they cost
// ~40 cyc each (~500 cyc). Window mass reads come from smem too; only ~9 iv
// loads per thread remain global (fixed trips -> unrolled -> MLP).

#define PS_B 128
#define PS_L 4096
#define PS_N 256
#define GROUPS 8                          // blocks per batch
#define PEAKS_PER_BLOCK (PS_N / GROUPS)   // 32
#define LANES 8                           // lanes per peak
#define THREADS (PEAKS_PER_BLOCK * LANES) // 256
#define LOG2E 1.4426950408889634f

__global__ __launch_bounds__(THREADS)
void peaksense_kernel(const float* __restrict__ mu,
                      const float* __restrict__ lv,
                      const float* __restrict__ masses,
                      const float* __restrict__ intens,
                      float* __restrict__ out) {
    __shared__ float sm_mass[PS_L];

    const int b    = blockIdx.y;
    const int tid  = threadIdx.x;
    const int p    = blockIdx.x * PEAKS_PER_BLOCK + (tid >> 3);
    const int q    = tid & 7;             // lane within peak group
    const int lane = tid & 31;

    // Stage this batch's masses into shared (float4, 4 per thread, MLP=4).
    {
        const float4* m4 = reinterpret_cast<const float4*>(masses + (size_t)b * PS_L);
        float4* s4 = reinterpret_cast<float4*>(sm_mass);
        #pragma unroll
        for (int i = tid; i < PS_L / 4; i += THREADS) s4[i] = m4[i];
    }

    const float* __restrict__ iv = intens + (size_t)b * PS_L;

    const float m      = mu[p];
    const float inv_s2 = __expf(-lv[p]);  // 1/sigma^2
    // arg >= -10  <=>  d^2 <= 20/inv_s2. Inflate R slightly so [lo,hi) is a
    // superset of the passing set; the exact in-loop select is the filter.
    const float R   = sqrtf(20.0f / inv_s2) * 1.0002f + 1e-5f;
    const float lob = m - R;
    const float hib = m + R;

    __syncthreads();

    // Lanes 0-3 of each peak group: lo = first index with mass >= lob.
    // Lanes 4-7: hi = first index with mass > hib. All probes hit smem.
    const bool  isLo   = (q < 4);
    const float target = isLo ? lob : hib;
    int slo = 0, shi = PS_L;
    #pragma unroll 1
    while (slo < shi) {
        int mid = (slo + shi) >> 1;
        float v = sm_mass[mid];
        bool goRight = isLo ? (v < target) : (v <= target);
        if (goRight) slo = mid + 1; else shi = mid;
    }
    const int base = lane & ~7;           // first lane of this peak group
    const int lo = __shfl_sync(0xFFFFFFFF, slo, base + 0);
    const int hi = __shfl_sync(0xFFFFFFFF, slo, base + 4);

    // w = exp2(c2*d*d), keep iff c2*d*d >= -10*log2(e).
    const float c2  = -0.5f * inv_s2 * LOG2E;
    const float th2 = -10.0f * LOG2E;

    float acc = 0.0f;
    #pragma unroll 4
    for (int i = lo + q; i < hi; i += LANES) {
        float d = sm_mass[i] - m;
        float a = c2 * d * d;
        float w = (a >= th2) ? exp2f(a) : 0.0f;
        acc = fmaf(w, iv[i], acc);        // iv load: global, batched by unroll
    }

    // Reduce the 8 lanes of this peak.
    acc += __shfl_xor_sync(0xFFFFFFFF, acc, 1);
    acc += __shfl_xor_sync(0xFFFFFFFF, acc, 2);
    acc += __shfl_xor_sync(0xFFFFFFFF, acc, 4);

    if (q == 0) out[(size_t)b * PS_N + p] = acc;
}

extern "C" void kernel_launch(void* const* d_in, const int* in_sizes, int n_in,
                              void* d_out, int out_size) {
    const float* mu     = (const float*)d_in[0];
    const float* lv     = (const float*)d_in[1];
    const float* masses = (const float*)d_in[2];
    const float* intens = (const float*)d_in[3];
    float* out = (float*)d_out;

    dim3 grid(GROUPS, PS_B);
    peaksense_kernel<<<grid, THREADS>>>(mu, lv, masses, intens, out);
}